// round 1
// baseline (speedup 1.0000x reference)
#include <cuda_runtime.h>
#include <math.h>

#define TT 2048
#define BB 64
#define II 128
#define HH 256
#define NBLK 128
#define NTHR 256
#define KTOT (HH + II)   /* 384: k = [h(256) ; x(128)] */
#define KCH  (KTOT / 8)  /* 48 k-values per k-chunk (8 chunks) */

// ---- device scratch (static: no allocation at runtime) ----
__device__ float g_xT[(size_t)TT * II * BB];   // x transposed: [t][i][b]
__device__ float g_hbuf[2][HH * BB];           // double-buffered h: [buf][j][b]
__device__ unsigned g_bar = 0;                 // grid-barrier arrive counter
__device__ unsigned g_gen = 0;                 // grid-barrier generation

// ============================================================
// Kernel 1: transpose x [b][t][i] -> g_xT [t][i][b]
// ============================================================
__global__ void __launch_bounds__(256) xpose_kernel(const float* __restrict__ x)
{
    __shared__ float xs[BB * (II + 1)];   // +1 pad: conflict-free transposed reads
    const int t = blockIdx.x;
    // coalesced loads: each b-row of 128 floats is contiguous
    for (int idx = threadIdx.x; idx < BB * II; idx += 256) {
        int b = idx >> 7, i = idx & 127;
        xs[b * (II + 1) + i] = x[((size_t)b * TT + t) * II + i];
    }
    __syncthreads();
    // coalesced stores to [t][i][b]
    float* dst = g_xT + (size_t)t * (II * BB);
    for (int idx = threadIdx.x; idx < II * BB; idx += 256) {
        int i = idx >> 6, b = idx & 63;
        dst[idx] = xs[b * (II + 1) + i];
    }
}

// ============================================================
// Kernel 2: persistent LSTM recurrence.
// 128 blocks, block bid owns hidden indices j0=2*bid, j0+1 (8 gate columns).
// SMEM layout (floats):
//   ws  [384*8]  @0      : weight slice, ws[k*8 + lc], lc = gate*2 + jj
//   hx  [384*64] @3072   : [k][b] concatenated h_prev (k<256) and x_t (k>=256)
//   red [4096]   @27648  : k-chunk partials red[lc*512 + b*8 + kc]
//   cs  [128]    @31744  : c-state for (b, jj)
//   bs  [8]      @31872  : bias slice
// ============================================================
#define SMEM_FLOATS 31880
#define SMEM_BYTES  (SMEM_FLOATS * 4)

__global__ void __launch_bounds__(NTHR, 1) lstm_kernel(
    const float* __restrict__ Wx, const float* __restrict__ Wh,
    const float* __restrict__ bias, float* __restrict__ out)
{
    extern __shared__ float sm[];
    float* ws  = sm;
    float* hx  = sm + 3072;
    float* red = sm + 27648;
    float* cs  = sm + 31744;
    float* bs  = sm + 31872;

    const int tid = threadIdx.x;
    const int j0  = blockIdx.x * 2;

    // ---- one-time: load this block's weight slice into SMEM ----
    // W_h[g][k_in][j_out], W_x[g][i][j_out]
    for (int idx = tid; idx < KTOT * 8; idx += NTHR) {
        int k = idx >> 3, lc = idx & 7;
        int g = lc >> 1, jj = lc & 1;
        ws[idx] = (k < HH)
            ? Wh[((size_t)g * HH + k) * HH + (j0 + jj)]
            : Wx[((size_t)g * II + (k - HH)) * HH + (j0 + jj)];
    }
    if (tid < 8)   bs[tid] = bias[(tid >> 1) * HH + j0 + (tid & 1)];
    if (tid < 128) cs[tid] = 0.f;   // c0 = 0 every launch (determinism)

    // thread -> (k-chunk, batch-group, col-group)
    const int kc  = tid >> 5;            // 0..7 (warp id = k-chunk)
    const int b0  = (tid & 15) * 4;      // 4 batches
    const int c0  = ((tid >> 4) & 1) * 4;// 4 of the 8 columns
    const int kbeg = kc * KCH;

    __syncthreads();

    for (int t = 0; t < TT; ++t) {
        // ---- stage h_prev (t>0) or zeros (t==0), then x_t ----
        if (t == 0) {
            float4 z = make_float4(0.f, 0.f, 0.f, 0.f);
            float4* d4 = (float4*)hx;
            for (int idx = tid; idx < (HH * BB) / 4; idx += NTHR) d4[idx] = z;
        } else {
            const float4* s4 = (const float4*)(g_hbuf[t & 1]);
            float4* d4 = (float4*)hx;
            for (int idx = tid; idx < (HH * BB) / 4; idx += NTHR)
                d4[idx] = __ldcg(s4 + idx);   // bypass L1: peer-SM writes
        }
        {
            const float4* s4 = (const float4*)(g_xT + (size_t)t * (II * BB));
            float4* d4 = (float4*)(hx + HH * BB);
            for (int idx = tid; idx < (II * BB) / 4; idx += NTHR)
                d4[idx] = s4[idx];
        }
        __syncthreads();

        // ---- GEMM partials: 4b x 4c tile over this thread's k-chunk ----
        float a[16];
        #pragma unroll
        for (int i = 0; i < 16; ++i) a[i] = 0.f;
        const float* hp = hx + kbeg * 64 + b0;
        const float* wp = ws + kbeg * 8 + c0;
        #pragma unroll 4
        for (int u = 0; u < KCH; ++u) {
            float4 hv = *(const float4*)(hp + u * 64);
            float4 wv = *(const float4*)(wp + u * 8);
            a[0]  += hv.x * wv.x; a[1]  += hv.x * wv.y; a[2]  += hv.x * wv.z; a[3]  += hv.x * wv.w;
            a[4]  += hv.y * wv.x; a[5]  += hv.y * wv.y; a[6]  += hv.y * wv.z; a[7]  += hv.y * wv.w;
            a[8]  += hv.z * wv.x; a[9]  += hv.z * wv.y; a[10] += hv.z * wv.z; a[11] += hv.z * wv.w;
            a[12] += hv.w * wv.x; a[13] += hv.w * wv.y; a[14] += hv.w * wv.z; a[15] += hv.w * wv.w;
        }
        #pragma unroll
        for (int r = 0; r < 4; ++r) {
            #pragma unroll
            for (int c = 0; c < 4; ++c)
                red[(c0 + c) * 512 + (b0 + r) * 8 + kc] = a[r * 4 + c];
        }
        __syncthreads();

        // ---- reduce over k-chunks, gate activations, state update ----
        if (tid < 128) {
            int b = tid >> 1, jj = tid & 1;
            float pg[4];
            #pragma unroll
            for (int g = 0; g < 4; ++g) {
                int lc = g * 2 + jj;
                const float* rp = red + lc * 512 + b * 8;
                pg[g] = ((rp[0] + rp[1]) + (rp[2] + rp[3]))
                      + ((rp[4] + rp[5]) + (rp[6] + rp[7])) + bs[lc];
            }
            float ig = 1.f / (1.f + __expf(-pg[0]));
            float fg = 1.f / (1.f + __expf(-pg[1]));
            float gg = tanhf(pg[2]);
            float og = 1.f / (1.f + __expf(-pg[3]));
            float cv = fg * cs[tid] + ig * gg;
            cs[tid] = cv;
            float hv = og * tanhf(cv);
            g_hbuf[(t & 1) ^ 1][(j0 + jj) * BB + b] = hv;
            out[((size_t)b * TT + t) * HH + (j0 + jj)] = hv;
        }

        // ---- grid barrier (release h writes, acquire peers') ----
        __threadfence();      // writers' stores ordered before arrive
        __syncthreads();
        if (tid == 0) {
            unsigned gen = *(volatile unsigned*)&g_gen;
            unsigned ticket = atomicAdd(&g_bar, 1u);
            if (ticket == NBLK - 1) {
                g_bar = 0;
                __threadfence();
                atomicExch(&g_gen, gen + 1u);   // release
            } else {
                while (*(volatile unsigned*)&g_gen == gen) { /* spin */ }
            }
        }
        __syncthreads();
    }
}

// ============================================================
extern "C" void kernel_launch(void* const* d_in, const int* in_sizes, int n_in,
                              void* d_out, int out_size)
{
    const float* x  = (const float*)d_in[0];   // [B, T, I]
    const float* Wx = (const float*)d_in[1];   // [4, I, H]
    const float* Wh = (const float*)d_in[2];   // [4, H, H]
    const float* b  = (const float*)d_in[3];   // [4, H]
    float* out = (float*)d_out;                // [B, T, H]

    cudaFuncSetAttribute(lstm_kernel,
                         cudaFuncAttributeMaxDynamicSharedMemorySize, SMEM_BYTES);

    xpose_kernel<<<TT, 256>>>(x);
    lstm_kernel<<<NBLK, NTHR, SMEM_BYTES>>>(Wx, Wh, b, out);
}

// round 2
// speedup vs baseline: 1.2367x; 1.2367x over previous
#include <cuda_runtime.h>
#include <math.h>

#define TT 2048
#define BB 64
#define II 128
#define HH 256
#define NBLK 128
#define NTHR 512
#define KTOT (HH + II)       /* 384: k = [h(256) ; x(128)] */
#define HXS  68              /* hx row stride (64 + 4 pad): conflict-free LDS.128 */

// ---- device scratch (static: no runtime allocation) ----
__device__ float g_xT[(size_t)TT * II * BB];   // x transposed: [t][i][b]
__device__ float g_hbuf[2][HH * BB];           // double-buffered h: [buf][j][b]
__device__ unsigned g_bar = 0;
__device__ unsigned g_gen = 0;

// ============================================================
// Kernel 1: transpose x [b][t][i] -> g_xT [t][i][b]
// ============================================================
__global__ void __launch_bounds__(256) xpose_kernel(const float* __restrict__ x)
{
    __shared__ float xs[BB * (II + 1)];
    const int t = blockIdx.x;
    for (int idx = threadIdx.x; idx < BB * II; idx += 256) {
        int b = idx >> 7, i = idx & 127;
        xs[b * (II + 1) + i] = x[((size_t)b * TT + t) * II + i];
    }
    __syncthreads();
    float* dst = g_xT + (size_t)t * (II * BB);
    for (int idx = threadIdx.x; idx < II * BB; idx += 256) {
        int i = idx >> 6, b = idx & 63;
        dst[idx] = xs[b * (II + 1) + i];
    }
}

// ============================================================
// Kernel 2: persistent LSTM.
// 128 blocks x 512 threads. Block owns j0=2*bid (+0,+1) -> 8 gate columns.
// Warp w owns batches b = 4w..4w+3. Lane l owns k-slice {l, l+32, ..., l+352}.
// Each lane: acc[r*8+c] partial over its 12 k values (4 b x 8 cols).
// In-warp butterfly reduce-scatter -> lane l holds output o=l fully reduced.
// SMEM (floats): ws[8*384] @0 (transposed: ws[c*384+k]),
//                hx[384*68] @3072, bs[8] @29184
// ============================================================
#define SM_WS 0
#define SM_HX 3072
#define SM_BS (3072 + KTOT * HXS)
#define SMEM_FLOATS (SM_BS + 8)
#define SMEM_BYTES (SMEM_FLOATS * 4)

__global__ void __launch_bounds__(NTHR, 1) lstm_kernel(
    const float* __restrict__ Wx, const float* __restrict__ Wh,
    const float* __restrict__ bias, float* __restrict__ out)
{
    extern __shared__ float sm[];
    float* ws = sm + SM_WS;
    float* hx = sm + SM_HX;
    float* bs = sm + SM_BS;

    const int tid  = threadIdx.x;
    const int w    = tid >> 5;
    const int lane = tid & 31;
    const int j0   = blockIdx.x * 2;

    // ---- one-time: weight slice, transposed ws[c][k] ----
    for (int idx = tid; idx < 8 * KTOT; idx += NTHR) {
        int c = idx / KTOT, k = idx - c * KTOT;
        int g = c >> 1, jj = c & 1;
        ws[c * KTOT + k] = (k < HH)
            ? Wh[((size_t)g * HH + k) * HH + (j0 + jj)]
            : Wx[((size_t)g * II + (k - HH)) * HH + (j0 + jj)];
    }
    if (tid < 8) bs[tid] = bias[(tid >> 1) * HH + j0 + (tid & 1)];

    // c-state in registers: lanes with (lane&7)<2 hold c for (b = 4w + (lane>>3), jj = lane&1)
    float creg = 0.f;
    const int jj   = lane & 1;
    const int myb  = w * 4 + (lane >> 3);
    const int base = lane & 24;
    const bool upd = (lane & 7) < 2;

    __syncthreads();

    for (int t = 0; t < TT; ++t) {
        // ---- stage h (rows 0..255) and x_t (rows 256..383) into hx[k*68 + b] ----
        if (t == 0) {
            float4 z = make_float4(0.f, 0.f, 0.f, 0.f);
            for (int idx = tid; idx < HH * 16; idx += NTHR) {
                int row = idx >> 4, c4 = (idx & 15) << 2;
                *(float4*)(hx + row * HXS + c4) = z;
            }
        } else {
            const float4* s4 = (const float4*)(g_hbuf[t & 1]);
            for (int idx = tid; idx < HH * 16; idx += NTHR) {
                int row = idx >> 4, c4 = (idx & 15) << 2;
                *(float4*)(hx + row * HXS + c4) = __ldcg(s4 + idx);
            }
        }
        {
            const float4* s4 = (const float4*)(g_xT + (size_t)t * (II * BB));
            for (int idx = tid; idx < II * 16; idx += NTHR) {
                int row = idx >> 4, c4 = (idx & 15) << 2;
                *(float4*)(hx + (HH + row) * HXS + c4) = s4[idx];
            }
        }
        __syncthreads();

        // ---- GEMM partials over this lane's k-slice ----
        float acc[32];
        #pragma unroll
        for (int i = 0; i < 32; ++i) acc[i] = 0.f;
        #pragma unroll
        for (int u = 0; u < 12; ++u) {
            const int k = lane + (u << 5);
            float4 hv = *(const float4*)(hx + k * HXS + (w << 2));
            #pragma unroll
            for (int c = 0; c < 8; ++c) {
                float wv = ws[c * KTOT + k];
                acc[c]      += hv.x * wv;
                acc[8 + c]  += hv.y * wv;
                acc[16 + c] += hv.z * wv;
                acc[24 + c] += hv.w * wv;
            }
        }

        // ---- in-warp butterfly reduce-scatter: lane l <- sum over lanes of acc[l] ----
        #pragma unroll
        for (int n = 16; n >= 1; n >>= 1) {
            #pragma unroll
            for (int o = 0; o < n; ++o) {
                float lo = acc[o], hi = acc[o + n];
                float send = (lane & n) ? lo : hi;
                float keep = (lane & n) ? hi : lo;
                acc[o] = keep + __shfl_xor_sync(0xffffffffu, send, n);
            }
        }
        float pre = acc[0];   // pre-activation for output o = lane (b=myb if upd, col=lane&7)

        // ---- gather 4 gates of (myb, jj) into the update lanes, apply LSTM cell ----
        float pf = __shfl_sync(0xffffffffu, pre, base | (2 + jj));
        float pg = __shfl_sync(0xffffffffu, pre, base | (4 + jj));
        float po = __shfl_sync(0xffffffffu, pre, base | (6 + jj));
        if (upd) {
            float ig = 1.f / (1.f + __expf(-(pre + bs[jj])));
            float fg = 1.f / (1.f + __expf(-(pf + bs[2 + jj])));
            float gg = tanhf(pg + bs[4 + jj]);
            float og = 1.f / (1.f + __expf(-(po + bs[6 + jj])));
            creg = fg * creg + ig * gg;
            float hv = og * tanhf(creg);
            g_hbuf[(t & 1) ^ 1][(j0 + jj) * BB + myb] = hv;
            out[((size_t)myb * TT + t) * HH + (j0 + jj)] = hv;
        }

        // ---- grid barrier ----
        __threadfence();
        __syncthreads();
        if (tid == 0) {
            unsigned gen = *(volatile unsigned*)&g_gen;
            unsigned ticket = atomicAdd(&g_bar, 1u);
            if (ticket == NBLK - 1) {
                g_bar = 0;
                __threadfence();
                atomicExch(&g_gen, gen + 1u);
            } else {
                while (*(volatile unsigned*)&g_gen == gen) { }
            }
        }
        __syncthreads();
    }
}

// ============================================================
extern "C" void kernel_launch(void* const* d_in, const int* in_sizes, int n_in,
                              void* d_out, int out_size)
{
    const float* x  = (const float*)d_in[0];   // [B, T, I]
    const float* Wx = (const float*)d_in[1];   // [4, I, H]
    const float* Wh = (const float*)d_in[2];   // [4, H, H]
    const float* b  = (const float*)d_in[3];   // [4, H]
    float* out = (float*)d_out;                // [B, T, H]

    cudaFuncSetAttribute(lstm_kernel,
                         cudaFuncAttributeMaxDynamicSharedMemorySize, SMEM_BYTES);

    xpose_kernel<<<TT, 256>>>(x);
    lstm_kernel<<<NBLK, NTHR, SMEM_BYTES>>>(Wx, Wh, b, out);
}

// round 3
// speedup vs baseline: 1.5402x; 1.2455x over previous
#include <cuda_runtime.h>
#include <math.h>

#define TT 2048
#define BB 64
#define II 128
#define HH 256
#define NBLK 128
#define NTHR 512
#define KTOT 384            /* k = [h(256) ; x(128)] */
#define HXS  68             /* staged activation row stride: conflict-free LDS.128 */
#define WSS  12             /* ws row stride (8 cols + 4 pad): conflict-free LDS.128 */

// ---- device scratch (static) ----
__device__ __align__(16) float g_xT[(size_t)TT * II * BB];  // [t][i][b]
__device__ __align__(16) float g_hbuf[2][HH * BB];          // [buf][j][b]
__device__ unsigned g_bar = 0;
__device__ unsigned g_gen = 0;

// ---- cp.async helpers ----
__device__ __forceinline__ void cp16(float* smem_dst, const float* gmem_src) {
    unsigned s = (unsigned)__cvta_generic_to_shared(smem_dst);
    asm volatile("cp.async.cg.shared.global [%0], [%1], 16;" :: "r"(s), "l"(gmem_src));
}
#define CP_COMMIT() asm volatile("cp.async.commit_group;" ::: "memory")
#define CP_WAIT0()  asm volatile("cp.async.wait_group 0;" ::: "memory")
#define CP_WAIT1()  asm volatile("cp.async.wait_group 1;" ::: "memory")

// ============================================================
// Kernel 1: transpose x [b][t][i] -> g_xT [t][i][b]
// ============================================================
__global__ void __launch_bounds__(256) xpose_kernel(const float* __restrict__ x)
{
    __shared__ float xs[BB * (II + 1)];
    const int t = blockIdx.x;
    for (int idx = threadIdx.x; idx < BB * II; idx += 256) {
        int b = idx >> 7, i = idx & 127;
        xs[b * (II + 1) + i] = x[((size_t)b * TT + t) * II + i];
    }
    __syncthreads();
    float* dst = g_xT + (size_t)t * (II * BB);
    for (int idx = threadIdx.x; idx < II * BB; idx += 256) {
        int i = idx >> 6, b = idx & 63;
        dst[idx] = xs[b * (II + 1) + i];
    }
}

// ============================================================
// Kernel 2: persistent LSTM, software-pipelined step.
// 128 blocks x 512 thr. Block owns j0=2*bid (8 gate cols).
// Warp w: batches 4w..4w+3. Lane l: k-slice {l, l+32, ...}.
// SMEM layout (floats):
//   ws [384*12] @0       : ws[k*12 + c]  (c = gate*2 + jj, 4 pad)
//   h  [256*68] @4608    : staged h_prev [k][b]
//   x  [2][128*68] @22016: double-buffered x_t [i][b]
//   bs [8] @39424
// ============================================================
#define SM_WS 0
#define SM_H  (KTOT * WSS)            /* 4608  */
#define SM_X  (SM_H + HH * HXS)       /* 22016 */
#define XBUF  (II * HXS)              /* 8704  */
#define SM_BS (SM_X + 2 * XBUF)       /* 39424 */
#define SMEM_FLOATS (SM_BS + 8)
#define SMEM_BYTES  (SMEM_FLOATS * 4)

#define FMA8(hvc, w0, w1, o) \
    acc[o+0] += (hvc) * (w0).x; acc[o+1] += (hvc) * (w0).y; \
    acc[o+2] += (hvc) * (w0).z; acc[o+3] += (hvc) * (w0).w; \
    acc[o+4] += (hvc) * (w1).x; acc[o+5] += (hvc) * (w1).y; \
    acc[o+6] += (hvc) * (w1).z; acc[o+7] += (hvc) * (w1).w;

__global__ void __launch_bounds__(NTHR, 1) lstm_kernel(
    const float* __restrict__ Wx, const float* __restrict__ Wh,
    const float* __restrict__ bias, float* __restrict__ out)
{
    extern __shared__ float sm[];
    float* ws = sm + SM_WS;
    float* bs = sm + SM_BS;

    const int tid  = threadIdx.x;
    const int w    = tid >> 5;
    const int lane = tid & 31;
    const int j0   = blockIdx.x * 2;
    const int bw   = w << 2;

    // one-time: weight slice ws[k*12 + c]
    for (int idx = tid; idx < KTOT * 8; idx += NTHR) {
        int k = idx >> 3, c = idx & 7;
        int g = c >> 1, jj2 = c & 1;
        ws[k * WSS + c] = (k < HH)
            ? Wh[((size_t)g * HH + k) * HH + (j0 + jj2)]
            : Wx[((size_t)g * II + (k - HH)) * HH + (j0 + jj2)];
    }
    if (tid < 8) bs[tid] = bias[(tid >> 1) * HH + j0 + (tid & 1)];

    float creg = 0.f;
    const int  jj   = lane & 1;
    const int  myb  = w * 4 + (lane >> 3);
    const int  base = lane & 24;
    const bool upd  = (lane & 7) < 2;

    // prologue: prefetch x_0 (2048 float4, 4 per thread)
    {
        const float* src = g_xT;
        float* dst = sm + SM_X;
        #pragma unroll
        for (int i = 0; i < 4; ++i) {
            int idx = tid + i * NTHR;
            int row = idx >> 4, c4 = (idx & 15) << 2;
            cp16(dst + row * HXS + c4, src + idx * 4);
        }
        CP_COMMIT();
    }
    __syncthreads();   // ws/bs ready

    for (int t = 0; t < TT; ++t) {
        if (t > 0) {
            // ---- grid barrier: h_t now globally visible ----
            __syncthreads();          // all warps done with step t-1
            if (tid == 0) {
                unsigned gen = *(volatile unsigned*)&g_gen;
                unsigned ticket = atomicAdd(&g_bar, 1u);
                if (ticket == NBLK - 1) {
                    g_bar = 0;
                    __threadfence();
                    atomicExch(&g_gen, gen + 1u);
                } else {
                    while (*(volatile unsigned*)&g_gen == gen) { }
                }
            }
            __syncthreads();

            // ---- issue h staging copies (fire-and-forget) ----
            const float* src = g_hbuf[t & 1];
            float* dst = sm + SM_H;
            #pragma unroll
            for (int i = 0; i < 8; ++i) {
                int idx = tid + i * NTHR;
                int row = idx >> 4, c4 = (idx & 15) << 2;
                cp16(dst + row * HXS + c4, src + idx * 4);
            }
            CP_COMMIT();
            CP_WAIT1();               // X_t done (H_t still in flight)
        } else {
            CP_WAIT0();               // X_0 done
        }
        __syncthreads();

        float acc[32];
        #pragma unroll
        for (int i = 0; i < 32; ++i) acc[i] = 0.f;

        // ---- x-part (k = 256..383) — hides H_t staging latency ----
        {
            const float* xb = sm + SM_X + (t & 1) * XBUF;
            #pragma unroll
            for (int u = 0; u < 4; ++u) {
                const int kr = lane + (u << 5);     // x row 0..127
                float4 hv = *(const float4*)(xb + kr * HXS + bw);
                float4 w0 = *(const float4*)(ws + (HH + kr) * WSS);
                float4 w1 = *(const float4*)(ws + (HH + kr) * WSS + 4);
                FMA8(hv.x, w0, w1, 0)
                FMA8(hv.y, w0, w1, 8)
                FMA8(hv.z, w0, w1, 16)
                FMA8(hv.w, w0, w1, 24)
            }
        }

        // ---- prefetch x_{t+1} into the other buffer ----
        if (t + 1 < TT) {
            const float* src = g_xT + (size_t)(t + 1) * (II * BB);
            float* dst = sm + SM_X + ((t + 1) & 1) * XBUF;
            #pragma unroll
            for (int i = 0; i < 4; ++i) {
                int idx = tid + i * NTHR;
                int row = idx >> 4, c4 = (idx & 15) << 2;
                cp16(dst + row * HXS + c4, src + idx * 4);
            }
            CP_COMMIT();
        }

        // ---- h-part (k = 0..255); at t==0, h==0 contributes nothing ----
        if (t > 0) {
            if (t + 1 < TT) { CP_WAIT1(); } else { CP_WAIT0(); }
            __syncthreads();
            const float* hb = sm + SM_H;
            #pragma unroll
            for (int u = 0; u < 8; ++u) {
                const int k = lane + (u << 5);
                float4 hv = *(const float4*)(hb + k * HXS + bw);
                float4 w0 = *(const float4*)(ws + k * WSS);
                float4 w1 = *(const float4*)(ws + k * WSS + 4);
                FMA8(hv.x, w0, w1, 0)
                FMA8(hv.y, w0, w1, 8)
                FMA8(hv.z, w0, w1, 16)
                FMA8(hv.w, w0, w1, 24)
            }
        }

        // ---- in-warp butterfly reduce-scatter: lane l <- full sum of output l ----
        #pragma unroll
        for (int n = 16; n >= 1; n >>= 1) {
            #pragma unroll
            for (int o = 0; o < n; ++o) {
                float lo = acc[o], hi = acc[o + n];
                float send = (lane & n) ? lo : hi;
                float keep = (lane & n) ? hi : lo;
                acc[o] = keep + __shfl_xor_sync(0xffffffffu, send, n);
            }
        }
        float pre = acc[0];

        // ---- gather gates, LSTM cell, write h ----
        float pf = __shfl_sync(0xffffffffu, pre, base | (2 + jj));
        float pg = __shfl_sync(0xffffffffu, pre, base | (4 + jj));
        float po = __shfl_sync(0xffffffffu, pre, base | (6 + jj));
        if (upd) {
            float ig = 1.f / (1.f + __expf(-(pre + bs[jj])));
            float fg = 1.f / (1.f + __expf(-(pf + bs[2 + jj])));
            float gg = tanhf(pg + bs[4 + jj]);
            float og = 1.f / (1.f + __expf(-(po + bs[6 + jj])));
            creg = fg * creg + ig * gg;
            float hv = og * tanhf(creg);
            g_hbuf[(t & 1) ^ 1][(j0 + jj) * BB + myb] = hv;
            out[((size_t)myb * TT + t) * HH + (j0 + jj)] = hv;
        }
        __threadfence();
    }
}

// ============================================================
extern "C" void kernel_launch(void* const* d_in, const int* in_sizes, int n_in,
                              void* d_out, int out_size)
{
    const float* x  = (const float*)d_in[0];   // [B, T, I]
    const float* Wx = (const float*)d_in[1];   // [4, I, H]
    const float* Wh = (const float*)d_in[2];   // [4, H, H]
    const float* b  = (const float*)d_in[3];   // [4, H]
    float* out = (float*)d_out;                // [B, T, H]

    cudaFuncSetAttribute(lstm_kernel,
                         cudaFuncAttributeMaxDynamicSharedMemorySize, SMEM_BYTES);

    xpose_kernel<<<TT, 256>>>(x);
    lstm_kernel<<<NBLK, NTHR, SMEM_BYTES>>>(Wx, Wh, b, out);
}